// round 13
// baseline (speedup 1.0000x reference)
#include <cuda_runtime.h>
#include <cuda_fp16.h>
#include <math_constants.h>

#define MAXN 20000
#define MAXE 320000
#define CAP  128   // max degree bucket capacity (degree ~ Poisson(16)+1; P(>50) ~ 1e-5)

// ---------------- scratch (device globals; no allocation) ----------------
__device__ __half2 g_h1h[MAXN * 128];   // h1 in half2: index p holds channels 2p,2p+1
__device__ float g_as1[MAXN * 4];
__device__ float g_ad1[MAXN * 4];
__device__ float g_h2[MAXN * 32];       // padded to 32 floats/row: 1 aligned line per row
__device__ float g_as2[MAXN];
__device__ float g_ad2[MAXN];
__device__ int   g_cnt[MAXN];           // zero at load; re-zeroed by k_agg2 each call
__device__ int   g_bkt[MAXN * CAP];
__device__ float g_w2t[21 * 256];       // W2 transposed [o][c]

__device__ __forceinline__ float leaky(float v) {
    return v > 0.f ? v : 0.2f * v;
}

// ---------------- fused front kernel: gemm1 (2 nodes/block) | scatter | W2 transpose ----
// g_cnt is already zero (loader on first call, k_agg2 epilogue on later calls),
// so the gemm1 and scatter roles are fully independent and overlap.
__global__ void k_front(const float* __restrict__ x, const float* __restrict__ W1,
                        const float* __restrict__ asrc, const float* __restrict__ adst,
                        const int* __restrict__ ei, const float* __restrict__ W2,
                        int N, int E, int G1, int SC) {
    int b = blockIdx.x;
    if (b < G1) {
        // ---- layer1 GEMM + alpha reductions: 128 threads per node, 2 nodes/block ----
        __shared__ float xs[2][3];
        int half = threadIdx.x >> 7;      // 0,1
        int t = threadIdx.x & 127;        // 0..127
        int n = b * 2 + half;
        if (n < N && t < 3) xs[half][t] = x[n * 3 + t];
        __syncthreads();
        if (n >= N) return;
        int c0 = 2 * t, c1 = 2 * t + 1;
        float h0  = fmaf(xs[half][0], W1[c0], fmaf(xs[half][1], W1[256 + c0], xs[half][2] * W1[512 + c0]));
        float h1v = fmaf(xs[half][0], W1[c1], fmaf(xs[half][1], W1[256 + c1], xs[half][2] * W1[512 + c1]));
        g_h1h[n * 128 + t] = __floats2half2_rn(h0, h1v);
        float ps = fmaf(h0, asrc[c0], h1v * asrc[c1]);
        float pd = fmaf(h0, adst[c0], h1v * adst[c1]);
#pragma unroll
        for (int d = 16; d; d >>= 1) {
            ps += __shfl_xor_sync(0xFFFFFFFFu, ps, d);
            pd += __shfl_xor_sync(0xFFFFFFFFu, pd, d);
        }
        if ((t & 31) == 0) {              // head = warp-within-half (channels 64h..64h+63)
            g_as1[n * 4 + (t >> 5)] = ps;
            g_ad1[n * 4 + (t >> 5)] = pd;
        }
    } else if (b < G1 + SC) {
        // ---- bucket scatter: edges grouped by dst ----
        int i = (b - G1) * 256 + threadIdx.x;
        if (i >= E + N) return;
        int src, dst;
        if (i < E) { src = ei[i]; dst = ei[E + i]; }
        else       { src = i - E; dst = i - E; }
        int slot = atomicAdd(&g_cnt[dst], 1);
        if (slot < CAP) g_bkt[dst * CAP + slot] = src;
    } else {
        // ---- W2 transpose to [o][c] ----
        for (int idx = threadIdx.x; idx < 21 * 256; idx += 256)
            g_w2t[idx] = W2[(idx & 255) * 21 + (idx >> 8)];
    }
}

// ---------------- layer1 aggregation FUSED with layer2 GEMM: one warp per dst ----------
__global__ void k_agg1(const float* __restrict__ b1,
                       const float* __restrict__ asrc2, const float* __restrict__ adst2,
                       int N) {
    __shared__ __align__(16) float w_s[8][CAP * 4];  // 16 KB
    __shared__ int s_src[8][CAP];                    //  4 KB

    int t = threadIdx.x;
    int warp = (blockIdx.x * blockDim.x + t) >> 5;
    int wi = t >> 5;
    int lane = t & 31;
    if (warp >= N) return;
    int dst = warp;
    const float4 ad = *(const float4*)&g_ad1[dst * 4];
    int cnt = min(g_cnt[dst], CAP);
    const int* bp = g_bkt + dst * CAP;

    // pass 1: lane-parallel e-values in registers (<=4 edges/lane)
    float e[4][4];
    int   sr[4];
    float m[4] = {-CUDART_INF_F, -CUDART_INF_F, -CUDART_INF_F, -CUDART_INF_F};
#pragma unroll
    for (int tt = 0; tt < 4; tt++) {
        int k = lane + 32 * tt;
        if (k < cnt) {
            int src = bp[k];
            sr[tt] = src;
            float4 as = *(const float4*)&g_as1[src * 4];
            e[tt][0] = leaky(as.x + ad.x);
            e[tt][1] = leaky(as.y + ad.y);
            e[tt][2] = leaky(as.z + ad.z);
            e[tt][3] = leaky(as.w + ad.w);
            m[0] = fmaxf(m[0], e[tt][0]);
            m[1] = fmaxf(m[1], e[tt][1]);
            m[2] = fmaxf(m[2], e[tt][2]);
            m[3] = fmaxf(m[3], e[tt][3]);
        }
    }
#pragma unroll
    for (int d = 16; d; d >>= 1)
#pragma unroll
        for (int h = 0; h < 4; h++)
            m[h] = fmaxf(m[h], __shfl_xor_sync(0xFFFFFFFFu, m[h], d));

    // weights + segment sums, stash (w, src) in shared
    float s[4] = {0.f, 0.f, 0.f, 0.f};
#pragma unroll
    for (int tt = 0; tt < 4; tt++) {
        int k = lane + 32 * tt;
        if (k < cnt) {
            float w0 = __expf(e[tt][0] - m[0]);
            float w1 = __expf(e[tt][1] - m[1]);
            float w2 = __expf(e[tt][2] - m[2]);
            float w3 = __expf(e[tt][3] - m[3]);
            s[0] += w0; s[1] += w1; s[2] += w2; s[3] += w3;
            *(float4*)&w_s[wi][k * 4] = make_float4(w0, w1, w2, w3);
            s_src[wi][k] = sr[tt];
        }
    }
#pragma unroll
    for (int d = 16; d; d >>= 1)
#pragma unroll
        for (int h = 0; h < 4; h++)
            s[h] += __shfl_xor_sync(0xFFFFFFFFu, s[h], d);
    __syncwarp();

    // pass 2: whole warp per edge, coalesced 512B half2 row of h1.
    // half2 index p = lane+32*jj -> channels 2p,2p+1, head = jj exactly.
    float2 acc2[4];
#pragma unroll
    for (int jj = 0; jj < 4; jj++) acc2[jj] = make_float2(0.f, 0.f);
    for (int k = 0; k < cnt; k++) {
        float4 wv4 = *(const float4*)&w_s[wi][k * 4];  // LDS broadcast
        int src = s_src[wi][k];
        float wv[4] = {wv4.x, wv4.y, wv4.z, wv4.w};
        const __half2* hp = g_h1h + src * 128;
#pragma unroll
        for (int jj = 0; jj < 4; jj++) {
            float2 f = __half22float2(hp[lane + 32 * jj]);
            acc2[jj].x = fmaf(wv[jj], f.x, acc2[jj].x);
            acc2[jj].y = fmaf(wv[jj], f.y, acc2[jj].y);
        }
    }

    // finalize out1 row in registers: /sum + b1, ReLU
    float v0[4], v1[4];
#pragma unroll
    for (int jj = 0; jj < 4; jj++) {
        int p = lane + 32 * jj;
        float inv = 1.f / (s[jj] + 1e-16f);
        float2 bb = *(const float2*)&b1[2 * p];
        v0[jj] = fmaxf(fmaf(acc2[jj].x, inv, bb.x), 0.f);
        v1[jj] = fmaxf(fmaf(acc2[jj].y, inv, bb.y), 0.f);
    }

    // fused layer2 GEMM from global W2t (L1-resident 21.5KB table, lane-contiguous)
    float pacc[21];
#pragma unroll
    for (int o = 0; o < 21; o++) pacc[o] = 0.f;
#pragma unroll
    for (int jj = 0; jj < 4; jj++) {
        int p = lane + 32 * jj;
#pragma unroll
        for (int o = 0; o < 21; o++) {
            float2 wv = __ldg((const float2*)&g_w2t[o * 256 + 2 * p]);
            pacc[o] = fmaf(v0[jj], wv.x, fmaf(v1[jj], wv.y, pacc[o]));
        }
    }
#pragma unroll
    for (int d = 16; d; d >>= 1)
#pragma unroll
        for (int o = 0; o < 21; o++)
            pacc[o] += __shfl_xor_sync(0xFFFFFFFFu, pacc[o], d);

    if (lane == 0) {
        float as = 0.f, adv = 0.f;
#pragma unroll
        for (int o = 0; o < 21; o++) {
            g_h2[dst * 32 + o] = pacc[o];
            as  = fmaf(pacc[o], __ldg(&asrc2[o]), as);
            adv = fmaf(pacc[o], __ldg(&adst2[o]), adv);
        }
        g_as2[dst] = as;
        g_ad2[dst] = adv;
    }
}

// ---------------- layer2 aggregation + final row softmax: warp per node ----------------
// Also re-zeroes g_cnt for the next invocation (after its last read).
__global__ void k_agg2(const float* __restrict__ b2, float* __restrict__ out, int N) {
    __shared__ float w_s[8][CAP];
    __shared__ int s_src[8][CAP];
    int warp = (blockIdx.x * blockDim.x + threadIdx.x) >> 5;
    int wi = threadIdx.x >> 5;
    int lane = threadIdx.x & 31;
    if (warp >= N) return;
    int dst = warp;
    float ad = g_ad2[dst];
    int cnt = min(g_cnt[dst], CAP);
    if (lane == 0) g_cnt[dst] = 0;   // reset for next call (first call: loader zero-init)
    const int* bp = g_bkt + dst * CAP;

    float e[4];
    int sr[4];
    float m = -CUDART_INF_F;
#pragma unroll
    for (int t = 0; t < 4; t++) {
        int k = lane + 32 * t;
        if (k < cnt) {
            int src = bp[k];
            sr[t] = src;
            e[t] = leaky(g_as2[src] + ad);
            m = fmaxf(m, e[t]);
        }
    }
#pragma unroll
    for (int d = 16; d; d >>= 1) m = fmaxf(m, __shfl_xor_sync(0xFFFFFFFFu, m, d));

    float s = 0.f;
#pragma unroll
    for (int t = 0; t < 4; t++) {
        int k = lane + 32 * t;
        if (k < cnt) {
            float w = __expf(e[t] - m);
            s += w;
            w_s[wi][k] = w;
            s_src[wi][k] = sr[t];
        }
    }
#pragma unroll
    for (int d = 16; d; d >>= 1) s += __shfl_xor_sync(0xFFFFFFFFu, s, d);
    __syncwarp();

    float a = 0.f;
    for (int k = 0; k < cnt; k++) {
        float w = w_s[wi][k];
        int src = s_src[wi][k];
        if (lane < 21) a = fmaf(w, g_h2[src * 32 + lane], a);  // 1 aligned 128B line
    }
    float v = (lane < 21) ? (a / (s + 1e-16f) + b2[lane]) : -CUDART_INF_F;

    // row softmax over 21 lanes
    float rm = v;
#pragma unroll
    for (int d = 16; d; d >>= 1) rm = fmaxf(rm, __shfl_xor_sync(0xFFFFFFFFu, rm, d));
    float ex = (lane < 21) ? __expf(v - rm) : 0.f;
    float ss = ex;
#pragma unroll
    for (int d = 16; d; d >>= 1) ss += __shfl_xor_sync(0xFFFFFFFFu, ss, d);
    if (lane < 21) out[dst * 21 + lane] = ex / ss;
}

// ---------------- launch ----------------
extern "C" void kernel_launch(void* const* d_in, const int* in_sizes, int n_in,
                              void* d_out, int out_size) {
    const float* x     = (const float*)d_in[0];
    const int*   ei    = (const int*)d_in[1];
    const float* W1    = (const float*)d_in[2];
    const float* asrc1 = (const float*)d_in[3];
    const float* adst1 = (const float*)d_in[4];
    const float* b1    = (const float*)d_in[5];
    const float* W2    = (const float*)d_in[6];
    const float* asrc2 = (const float*)d_in[7];
    const float* adst2 = (const float*)d_in[8];
    const float* b2    = (const float*)d_in[9];
    float* out = (float*)d_out;

    int N = in_sizes[0] / 3;
    int E = in_sizes[1] / 2;
    int T = E + N;
    int G1 = (N + 1) / 2;
    int SC = (T + 255) / 256;

    k_front<<<G1 + SC + 1, 256>>>(x, W1, asrc1, adst1, ei, W2, N, E, G1, SC);
    k_agg1<<<(N + 7) / 8, 256>>>(b1, asrc2, adst2, N);
    k_agg2<<<(N + 7) / 8, 256>>>(b2, out, N);
}

// round 14
// speedup vs baseline: 1.1666x; 1.1666x over previous
#include <cuda_runtime.h>
#include <cuda_fp16.h>
#include <math_constants.h>

#define MAXN 20000
#define MAXE 320000
#define CAP  128   // max degree bucket capacity (degree ~ Poisson(16)+1; P(>50) ~ 1e-5)

// ---------------- scratch (device globals; no allocation) ----------------
__device__ __half2 g_h1h[MAXN * 128];   // h1 in half2: index p holds channels 2p,2p+1
__device__ float g_as1[MAXN * 4];
__device__ float g_ad1[MAXN * 4];
__device__ float g_h2[MAXN * 32];       // padded: one aligned 128B line per row
__device__ float g_as2[MAXN];
__device__ float g_ad2[MAXN];
__device__ int   g_cnt[MAXN];
__device__ int   g_bkt[MAXN * CAP];

__device__ __forceinline__ float leaky(float v) {
    return v > 0.f ? v : 0.2f * v;
}

// ---------------- layer1 GEMM + alpha reductions: 128 threads per node ----------------
// Thread t computes channels 2t, 2t+1 (head = warp id). Also zeroes g_cnt.
__global__ void k_gemm1(const float* __restrict__ x, const float* __restrict__ W1,
                        const float* __restrict__ asrc, const float* __restrict__ adst,
                        int N) {
    int n = blockIdx.x;
    int t = threadIdx.x;  // 0..127
    __shared__ float xs[3];
    if (t < 3) xs[t] = x[n * 3 + t];
    if (t == 4) g_cnt[n] = 0;
    __syncthreads();
    int c0 = 2 * t, c1 = 2 * t + 1;
    float h0  = fmaf(xs[0], W1[c0], fmaf(xs[1], W1[256 + c0], xs[2] * W1[512 + c0]));
    float h1v = fmaf(xs[0], W1[c1], fmaf(xs[1], W1[256 + c1], xs[2] * W1[512 + c1]));
    g_h1h[n * 128 + t] = __floats2half2_rn(h0, h1v);
    float ps = fmaf(h0, asrc[c0], h1v * asrc[c1]);
    float pd = fmaf(h0, adst[c0], h1v * adst[c1]);
#pragma unroll
    for (int d = 16; d; d >>= 1) {
        ps += __shfl_xor_sync(0xFFFFFFFFu, ps, d);
        pd += __shfl_xor_sync(0xFFFFFFFFu, pd, d);
    }
    if ((t & 31) == 0) {
        g_as1[n * 4 + (t >> 5)] = ps;
        g_ad1[n * 4 + (t >> 5)] = pd;
    }
}

// ---------------- bucket scatter: edges grouped by dst ----------------
__global__ void k_scatter(const int* __restrict__ ei, int E, int N) {
    int i = blockIdx.x * blockDim.x + threadIdx.x;
    if (i >= E + N) return;
    int src, dst;
    if (i < E) { src = ei[i]; dst = ei[E + i]; }
    else       { src = i - E; dst = i - E; }
    int slot = atomicAdd(&g_cnt[dst], 1);
    if (slot < CAP) g_bkt[dst * CAP + slot] = src;
}

// ---------------- layer1 aggregation FUSED with layer2 GEMM: one warp per dst ----------
__global__ void k_agg1(const float* __restrict__ b1, const float* __restrict__ W2,
                       const float* __restrict__ asrc2, const float* __restrict__ adst2,
                       int N) {
    __shared__ __align__(16) float W2t[21 * 256];    // [o][c] transposed, 21 KB
    __shared__ __align__(16) float w_s[8][CAP * 4];  // 16 KB
    __shared__ int s_src[8][CAP];                    //  4 KB

    int t = threadIdx.x;
    // cooperative load + transpose of W2: W2t[o*256+c] = W2[c*21+o]
    for (int idx = t; idx < 21 * 256; idx += 256)
        W2t[idx] = W2[(idx & 255) * 21 + (idx >> 8)];
    __syncthreads();

    int warp = (blockIdx.x * blockDim.x + t) >> 5;
    int wi = t >> 5;
    int lane = t & 31;
    if (warp >= N) return;
    int dst = warp;
    const float4 ad = *(const float4*)&g_ad1[dst * 4];
    int cnt = min(g_cnt[dst], CAP);
    const int* bp = g_bkt + dst * CAP;

    // pass 1: lane-parallel e-values in registers (<=4 edges/lane)
    float e[4][4];
    int   sr[4];
    float m[4] = {-CUDART_INF_F, -CUDART_INF_F, -CUDART_INF_F, -CUDART_INF_F};
#pragma unroll
    for (int tt = 0; tt < 4; tt++) {
        int k = lane + 32 * tt;
        if (k < cnt) {
            int src = bp[k];
            sr[tt] = src;
            float4 as = *(const float4*)&g_as1[src * 4];
            e[tt][0] = leaky(as.x + ad.x);
            e[tt][1] = leaky(as.y + ad.y);
            e[tt][2] = leaky(as.z + ad.z);
            e[tt][3] = leaky(as.w + ad.w);
            m[0] = fmaxf(m[0], e[tt][0]);
            m[1] = fmaxf(m[1], e[tt][1]);
            m[2] = fmaxf(m[2], e[tt][2]);
            m[3] = fmaxf(m[3], e[tt][3]);
        }
    }
#pragma unroll
    for (int d = 16; d; d >>= 1)
#pragma unroll
        for (int h = 0; h < 4; h++)
            m[h] = fmaxf(m[h], __shfl_xor_sync(0xFFFFFFFFu, m[h], d));

    // weights + segment sums, stash (w, src) in shared
    float s[4] = {0.f, 0.f, 0.f, 0.f};
#pragma unroll
    for (int tt = 0; tt < 4; tt++) {
        int k = lane + 32 * tt;
        if (k < cnt) {
            float w0 = __expf(e[tt][0] - m[0]);
            float w1 = __expf(e[tt][1] - m[1]);
            float w2 = __expf(e[tt][2] - m[2]);
            float w3 = __expf(e[tt][3] - m[3]);
            s[0] += w0; s[1] += w1; s[2] += w2; s[3] += w3;
            *(float4*)&w_s[wi][k * 4] = make_float4(w0, w1, w2, w3);
            s_src[wi][k] = sr[tt];
        }
    }
#pragma unroll
    for (int d = 16; d; d >>= 1)
#pragma unroll
        for (int h = 0; h < 4; h++)
            s[h] += __shfl_xor_sync(0xFFFFFFFFu, s[h], d);
    __syncwarp();

    // pass 2: whole warp per edge, coalesced 512B half2 rows, unrolled x2 for MLP
    float2 acc2[4];
#pragma unroll
    for (int jj = 0; jj < 4; jj++) acc2[jj] = make_float2(0.f, 0.f);
    int k = 0;
    for (; k + 2 <= cnt; k += 2) {
        float4 wa = *(const float4*)&w_s[wi][k * 4];
        float4 wb = *(const float4*)&w_s[wi][(k + 1) * 4];
        const __half2* ha = g_h1h + s_src[wi][k] * 128;
        const __half2* hb = g_h1h + s_src[wi][k + 1] * 128;
        __half2 ra[4], rb[4];
#pragma unroll
        for (int jj = 0; jj < 4; jj++) { ra[jj] = ha[lane + 32 * jj]; rb[jj] = hb[lane + 32 * jj]; }
        float wva[4] = {wa.x, wa.y, wa.z, wa.w};
        float wvb[4] = {wb.x, wb.y, wb.z, wb.w};
#pragma unroll
        for (int jj = 0; jj < 4; jj++) {
            float2 fa = __half22float2(ra[jj]);
            float2 fb = __half22float2(rb[jj]);
            acc2[jj].x = fmaf(wva[jj], fa.x, acc2[jj].x);
            acc2[jj].y = fmaf(wva[jj], fa.y, acc2[jj].y);
            acc2[jj].x = fmaf(wvb[jj], fb.x, acc2[jj].x);
            acc2[jj].y = fmaf(wvb[jj], fb.y, acc2[jj].y);
        }
    }
    for (; k < cnt; k++) {
        float4 wv4 = *(const float4*)&w_s[wi][k * 4];
        const __half2* hp = g_h1h + s_src[wi][k] * 128;
        float wv[4] = {wv4.x, wv4.y, wv4.z, wv4.w};
#pragma unroll
        for (int jj = 0; jj < 4; jj++) {
            float2 f = __half22float2(hp[lane + 32 * jj]);
            acc2[jj].x = fmaf(wv[jj], f.x, acc2[jj].x);
            acc2[jj].y = fmaf(wv[jj], f.y, acc2[jj].y);
        }
    }

    // finalize out1 row in registers: /sum + b1, ReLU
    float v0[4], v1[4];
#pragma unroll
    for (int jj = 0; jj < 4; jj++) {
        int p = lane + 32 * jj;
        float inv = 1.f / (s[jj] + 1e-16f);
        float2 bb = *(const float2*)&b1[2 * p];
        v0[jj] = fmaxf(fmaf(acc2[jj].x, inv, bb.x), 0.f);
        v1[jj] = fmaxf(fmaf(acc2[jj].y, inv, bb.y), 0.f);
    }

    // fused layer2 GEMM: pacc[o] = sum_c out1[c] * W2[c][o], conflict-free LDS.64
    float pacc[21];
#pragma unroll
    for (int o = 0; o < 21; o++) pacc[o] = 0.f;
#pragma unroll
    for (int jj = 0; jj < 4; jj++) {
        int p = lane + 32 * jj;
#pragma unroll
        for (int o = 0; o < 21; o++) {
            float2 wv = *(const float2*)&W2t[o * 256 + 2 * p];
            pacc[o] = fmaf(v0[jj], wv.x, fmaf(v1[jj], wv.y, pacc[o]));
        }
    }
#pragma unroll
    for (int d = 16; d; d >>= 1)
#pragma unroll
        for (int o = 0; o < 21; o++)
            pacc[o] += __shfl_xor_sync(0xFFFFFFFFu, pacc[o], d);

    if (lane == 0) {
        float as = 0.f, adv = 0.f;
#pragma unroll
        for (int o = 0; o < 21; o++) {
            g_h2[dst * 32 + o] = pacc[o];
            as  = fmaf(pacc[o], __ldg(&asrc2[o]), as);
            adv = fmaf(pacc[o], __ldg(&adst2[o]), adv);
        }
        g_as2[dst] = as;
        g_ad2[dst] = adv;
    }
}

// ---------------- layer2 aggregation + final row softmax: warp per node ----------------
__global__ void k_agg2(const float* __restrict__ b2, float* __restrict__ out, int N) {
    __shared__ float w_s[8][CAP];
    __shared__ int s_src[8][CAP];
    int warp = (blockIdx.x * blockDim.x + threadIdx.x) >> 5;
    int wi = threadIdx.x >> 5;
    int lane = threadIdx.x & 31;
    if (warp >= N) return;
    int dst = warp;
    float ad = g_ad2[dst];
    int cnt = min(g_cnt[dst], CAP);
    const int* bp = g_bkt + dst * CAP;

    float e[4];
    int sr[4];
    float m = -CUDART_INF_F;
#pragma unroll
    for (int t = 0; t < 4; t++) {
        int k = lane + 32 * t;
        if (k < cnt) {
            int src = bp[k];
            sr[t] = src;
            e[t] = leaky(g_as2[src] + ad);
            m = fmaxf(m, e[t]);
        }
    }
#pragma unroll
    for (int d = 16; d; d >>= 1) m = fmaxf(m, __shfl_xor_sync(0xFFFFFFFFu, m, d));

    float s = 0.f;
#pragma unroll
    for (int t = 0; t < 4; t++) {
        int k = lane + 32 * t;
        if (k < cnt) {
            float w = __expf(e[t] - m);
            s += w;
            w_s[wi][k] = w;
            s_src[wi][k] = sr[t];
        }
    }
#pragma unroll
    for (int d = 16; d; d >>= 1) s += __shfl_xor_sync(0xFFFFFFFFu, s, d);
    __syncwarp();

    // weighted gather of h2 rows, unrolled x4: 4 independent 128B lines in flight
    float a = 0.f;
    int k = 0;
    for (; k + 4 <= cnt; k += 4) {
        float w0 = w_s[wi][k],     w1 = w_s[wi][k + 1];
        float w2 = w_s[wi][k + 2], w3 = w_s[wi][k + 3];
        int s0 = s_src[wi][k],     s1 = s_src[wi][k + 1];
        int s2 = s_src[wi][k + 2], s3 = s_src[wi][k + 3];
        float h0 = 0.f, h1 = 0.f, h2v = 0.f, h3 = 0.f;
        if (lane < 21) {
            h0  = g_h2[s0 * 32 + lane];
            h1  = g_h2[s1 * 32 + lane];
            h2v = g_h2[s2 * 32 + lane];
            h3  = g_h2[s3 * 32 + lane];
        }
        a = fmaf(w0, h0, a);
        a = fmaf(w1, h1, a);
        a = fmaf(w2, h2v, a);
        a = fmaf(w3, h3, a);
    }
    for (; k < cnt; k++) {
        float w = w_s[wi][k];
        int src = s_src[wi][k];
        if (lane < 21) a = fmaf(w, g_h2[src * 32 + lane], a);
    }
    float v = (lane < 21) ? (a / (s + 1e-16f) + b2[lane]) : -CUDART_INF_F;

    // row softmax over 21 lanes
    float rm = v;
#pragma unroll
    for (int d = 16; d; d >>= 1) rm = fmaxf(rm, __shfl_xor_sync(0xFFFFFFFFu, rm, d));
    float ex = (lane < 21) ? __expf(v - rm) : 0.f;
    float ss = ex;
#pragma unroll
    for (int d = 16; d; d >>= 1) ss += __shfl_xor_sync(0xFFFFFFFFu, ss, d);
    if (lane < 21) out[dst * 21 + lane] = ex / ss;
}

// ---------------- launch ----------------
extern "C" void kernel_launch(void* const* d_in, const int* in_sizes, int n_in,
                              void* d_out, int out_size) {
    const float* x     = (const float*)d_in[0];
    const int*   ei    = (const int*)d_in[1];
    const float* W1    = (const float*)d_in[2];
    const float* asrc1 = (const float*)d_in[3];
    const float* adst1 = (const float*)d_in[4];
    const float* b1    = (const float*)d_in[5];
    const float* W2    = (const float*)d_in[6];
    const float* asrc2 = (const float*)d_in[7];
    const float* adst2 = (const float*)d_in[8];
    const float* b2    = (const float*)d_in[9];
    float* out = (float*)d_out;

    int N = in_sizes[0] / 3;
    int E = in_sizes[1] / 2;
    int T = E + N;

    k_gemm1<<<N, 128>>>(x, W1, asrc1, adst1, N);        // also zeroes g_cnt
    k_scatter<<<(T + 255) / 256, 256>>>(ei, E, N);
    k_agg1<<<(N + 7) / 8, 256>>>(b1, W2, asrc2, adst2, N);
    k_agg2<<<(N + 7) / 8, 256>>>(b2, out, N);
}